// round 2
// baseline (speedup 1.0000x reference)
#include <cuda_runtime.h>
#include <math.h>

// Problem constants (fixed by the dataset episode config)
#define NS   5760      // total images = B*(WAY*SHOT+NQ)*P = 8*80*9
#define CO   640       // conv output channels
#define KD   192       // 3*8*8 reduction dim
#define NPOS 16        // 4x4 conv output positions
#define B_   8
#define WAY_ 5
#define NQ_  75
#define P_   9

// Scratch: normalized pooled feature vectors u[sample][channel]
__device__ float g_u[(size_t)NS * CO];

__device__ __forceinline__ void fma2(unsigned long long& d,
                                     unsigned long long a,
                                     unsigned long long b) {
    asm("fma.rn.f32x2 %0, %1, %2, %0;" : "+l"(d) : "l"(a), "l"(b));
}
__device__ __forceinline__ unsigned long long pack2(float x, float y) {
    unsigned long long r;
    asm("mov.b64 %0, {%1, %2};" : "=l"(r) : "f"(x), "f"(y));
    return r;
}
__device__ __forceinline__ float2 unpack2(unsigned long long v) {
    float lo, hi;
    asm("mov.b64 {%0, %1}, %2;" : "=f"(lo), "=f"(hi) : "l"(v));
    return make_float2(lo, hi);
}

// ---------------------------------------------------------------------------
// Kernel 1: per-image conv GEMM (packed f32x2) + per-position channel L2-norm
// + avg-pool + final L2-norm. One block per image, 160 threads.
// Thread t owns channels {t, t+160, t+320, t+480}; positions packed in pairs.
// ---------------------------------------------------------------------------
__global__ void __launch_bounds__(160) k_conv(const float* __restrict__ data,
                                              const float* __restrict__ wgt) {
    __shared__ float xs[KD * NPOS];   // X rearranged [k][pos], 12 KB, rows 64B-aligned
    __shared__ float ssq[NPOS];
    __shared__ float red[5];
    __shared__ float s_invn;

    const int s = blockIdx.x;
    const int t = threadIdx.x;
    const float* img = data + (size_t)s * 3072;

    for (int i = t; i < 3072; i += 160) {
        float v = img[i];
        int ci  = i >> 10;
        int row = (i >> 5) & 31;
        int col = i & 31;
        int k   = ci * 64 + (row & 7) * 8 + (col & 7);
        int pos = (row >> 3) * 4 + (col >> 3);
        xs[k * NPOS + pos] = v;
    }
    if (t < NPOS) ssq[t] = 0.f;
    __syncthreads();

    // 4 channels x 8 position-pairs, packed f32x2 accumulators
    unsigned long long acc2[4][8];
#pragma unroll
    for (int c = 0; c < 4; c++)
#pragma unroll
        for (int p = 0; p < 8; p++) acc2[c][p] = 0ull;

    const float* wr = wgt + (size_t)t * KD;

    for (int k = 0; k < KD; k += 4) {
        float4 wv[4];
#pragma unroll
        for (int c = 0; c < 4; c++)
            wv[c] = *reinterpret_cast<const float4*>(wr + (size_t)c * 160 * KD + k);
#pragma unroll
        for (int kk = 0; kk < 4; kk++) {
            const ulonglong2* xr =
                reinterpret_cast<const ulonglong2*>(&xs[(k + kk) * NPOS]);
            ulonglong2 xa = xr[0], xb = xr[1], xc = xr[2], xd = xr[3];
            unsigned long long xp[8] = {xa.x, xa.y, xb.x, xb.y,
                                        xc.x, xc.y, xd.x, xd.y};
#pragma unroll
            for (int c = 0; c < 4; c++) {
                float wkc = (kk == 0) ? wv[c].x : (kk == 1) ? wv[c].y
                          : (kk == 2) ? wv[c].z : wv[c].w;
                unsigned long long w2 = pack2(wkc, wkc);
#pragma unroll
                for (int p = 0; p < 8; p++) fma2(acc2[c][p], w2, xp[p]);
            }
        }
    }

    // Per-position sum of squares over all 640 channels (pair-wise).
    const int lane = t & 31;
#pragma unroll
    for (int p2 = 0; p2 < 8; p2++) {
        float vlo = 0.f, vhi = 0.f;
#pragma unroll
        for (int c = 0; c < 4; c++) {
            float2 a = unpack2(acc2[c][p2]);
            vlo = fmaf(a.x, a.x, vlo);
            vhi = fmaf(a.y, a.y, vhi);
        }
#pragma unroll
        for (int off = 16; off; off >>= 1) {
            vlo += __shfl_xor_sync(0xffffffffu, vlo, off);
            vhi += __shfl_xor_sync(0xffffffffu, vhi, off);
        }
        if (lane == 0) {
            atomicAdd(&ssq[2 * p2], vlo);
            atomicAdd(&ssq[2 * p2 + 1], vhi);
        }
    }
    __syncthreads();

    float inv[NPOS];
#pragma unroll
    for (int p = 0; p < NPOS; p++)
        inv[p] = 1.f / fmaxf(sqrtf(ssq[p]), 1e-12f);

    float v4[4];
    float ss = 0.f;
#pragma unroll
    for (int c = 0; c < 4; c++) {
        float sum = 0.f;
#pragma unroll
        for (int p2 = 0; p2 < 8; p2++) {
            float2 a = unpack2(acc2[c][p2]);
            sum = fmaf(a.x, inv[2 * p2], sum);
            sum = fmaf(a.y, inv[2 * p2 + 1], sum);
        }
        v4[c] = sum * (1.f / 16.f);
        ss = fmaf(v4[c], v4[c], ss);
    }
#pragma unroll
    for (int off = 16; off; off >>= 1) ss += __shfl_xor_sync(0xffffffffu, ss, off);
    if (lane == 0) red[t >> 5] = ss;
    __syncthreads();
    if (t == 0) {
        float x = red[0] + red[1] + red[2] + red[3] + red[4];
        s_invn = 1.f / fmaxf(sqrtf(x), 1e-12f);
    }
    __syncthreads();
    float invn = s_invn;
#pragma unroll
    for (int c = 0; c < 4; c++)
        g_u[(size_t)s * CO + t + c * 160] = v4[c] * invn;
}

// ---------------------------------------------------------------------------
// Kernel 2: similarity matrix + greedy pruning.
// One block per (b, n, m): 3000 blocks, 256 threads. Each 81-element dot
// is split across 2 threads (320 channels each), partials combined via smem.
// ---------------------------------------------------------------------------
#define QSTRIDE 644

__global__ void __launch_bounds__(256) k_sim(float* __restrict__ out) {
    __shared__ float qsm[9 * QSTRIDE];
    __shared__ float ssm[9 * QSTRIDE];
    __shared__ float psum[162];
    __shared__ float simm[81];

    const int bid = blockIdx.x;
    const int m = bid % WAY_;
    const int n = (bid / WAY_) % NQ_;
    const int b = bid / (WAY_ * NQ_);
    const int t = threadIdx.x;

    const float* qb = g_u + ((size_t)(b * 80 + WAY_ + n) * P_) * CO;
    const float* sb = g_u + ((size_t)(b * 80 + m) * P_) * CO;
    for (int i = t; i < 9 * 160; i += 256) {
        int r = i / 160, c4 = (i % 160) * 4;
        *reinterpret_cast<float4*>(&qsm[r * QSTRIDE + c4]) =
            *reinterpret_cast<const float4*>(qb + (size_t)r * CO + c4);
        *reinterpret_cast<float4*>(&ssm[r * QSTRIDE + c4]) =
            *reinterpret_cast<const float4*>(sb + (size_t)r * CO + c4);
    }
    __syncthreads();

    if (t < 162) {
        const int pair = t >> 1;
        const int half = t & 1;
        const int h = pair / 9, wq = pair % 9;
        const float* sr = &ssm[h * QSTRIDE + half * 320];
        const float* qr = &qsm[wq * QSTRIDE + half * 320];
        float d = 0.f;
#pragma unroll 4
        for (int c = 0; c < 320; c += 4) {
            float4 a = *reinterpret_cast<const float4*>(sr + c);
            float4 q = *reinterpret_cast<const float4*>(qr + c);
            d = fmaf(a.x, q.x, d);
            d = fmaf(a.y, q.y, d);
            d = fmaf(a.z, q.z, d);
            d = fmaf(a.w, q.w, d);
        }
        psum[t] = d;
    }
    __syncthreads();
    if (t < 81) simm[t] = psum[2 * t] + psum[2 * t + 1];
    __syncthreads();

    // Greedy masked argmax x9, first-index tie-break (matches jnp.argmax).
    if (t < 32) {
        float v0 = simm[t];
        float v1 = simm[t + 32];
        float v2 = (t + 64 < 81) ? simm[t + 64] : -1e30f;
        unsigned rmask = 0x1FFu, cmask = 0x1FFu;
        float totalv = 0.f, beta = 1.f;
        for (int it = 0; it < 9; it++) {
            float bv = -1e30f;
            int bidx = 999;
            int j = t;
            if (((rmask >> (j / 9)) & 1) && ((cmask >> (j % 9)) & 1)) {
                bv = v0; bidx = j;
            }
            j = t + 32;
            if (((rmask >> (j / 9)) & 1) && ((cmask >> (j % 9)) & 1)) {
                if (v1 > bv || (v1 == bv && j < bidx)) { bv = v1; bidx = j; }
            }
            j = t + 64;
            if (j < 81 && ((rmask >> (j / 9)) & 1) && ((cmask >> (j % 9)) & 1)) {
                if (v2 > bv || (v2 == bv && j < bidx)) { bv = v2; bidx = j; }
            }
#pragma unroll
            for (int off = 16; off; off >>= 1) {
                float ov = __shfl_xor_sync(0xffffffffu, bv, off);
                int   oi = __shfl_xor_sync(0xffffffffu, bidx, off);
                if (ov > bv || (ov == bv && oi < bidx)) { bv = ov; bidx = oi; }
            }
            totalv = fmaf(fmaxf(bv, 0.f), beta, totalv);
            beta *= 0.5f;
            rmask &= ~(1u << (bidx / 9));
            cmask &= ~(1u << (bidx % 9));
        }
        if (t == 0) out[((size_t)b * NQ_ + n) * WAY_ + m] = totalv;
    }
}

// ---------------------------------------------------------------------------
extern "C" void kernel_launch(void* const* d_in, const int* in_sizes, int n_in,
                              void* d_out, int out_size) {
    const float* data   = (const float*)d_in[0];
    const float* conv_w = (const float*)d_in[1];
    (void)in_sizes; (void)n_in; (void)out_size;

    k_conv<<<NS, 160>>>(data, conv_w);
    k_sim<<<B_ * NQ_ * WAY_, 256>>>((float*)d_out);
}

// round 4
// speedup vs baseline: 2.0500x; 2.0500x over previous
#include <cuda_runtime.h>
#include <cuda_fp16.h>
#include <cstdint>
#include <math.h>

// ---------------- problem constants ----------------
#define NS   5760
#define CO   640
#define KD   192
#define NPOS 16
#define B_   8
#define WAY_ 5
#define NQ_  75
#define P_   9
#define NTOT (NS * NPOS)     // 92160
#define KE2  576             // 3 * 192 fp16-split K
#define TNB  64              // N per block = 4 images
#define NCH  18              // K chunks of 32

// ---------------- device scratch ----------------
__device__ __align__(128) __half g_X[(size_t)NTOT * KE2];  // 106 MB
__device__ __align__(128) __half g_W[(size_t)CO * KE2];    // 737 KB
__device__ float g_u[(size_t)NS * CO];

__device__ __forceinline__ uint32_t smem_u32(const void* p) {
    uint32_t a;
    asm("{ .reg .u64 t; cvta.to.shared.u64 t, %1; cvt.u32.u64 %0, t; }"
        : "=r"(a) : "l"(p));
    return a;
}

// ---------------------------------------------------------------------------
// Prep W: fp16 split, K-concat [w0 | w0 | w1]
// ---------------------------------------------------------------------------
__global__ void k_prepw(const float* __restrict__ w) {
    int i = blockIdx.x * 256 + threadIdx.x;
    if (i >= CO * KD) return;
    int ch = i / KD, k = i % KD;
    float v = w[i];
    __half h0 = __float2half_rn(v);
    __half h1 = __float2half_rn(v - __half2float(h0));
    size_t b = (size_t)ch * KE2;
    g_W[b + k]       = h0;
    g_W[b + 192 + k] = h0;
    g_W[b + 384 + k] = h1;
}

// ---------------------------------------------------------------------------
// Prep X: im2col + fp16 split, K-concat [x0 | x1 | x0]. One block per image.
// g_X row = s*16 + pos.
// ---------------------------------------------------------------------------
__global__ void __launch_bounds__(128) k_prepx(const float* __restrict__ data) {
    __shared__ __align__(16) __half xsm[NPOS * KE2];   // 18 KB
    const int s = blockIdx.x, t = threadIdx.x;
    const float* img = data + (size_t)s * 3072;
    for (int i = t; i < 3072; i += 128) {
        float v = img[i];
        int ci = i >> 10, row = (i >> 5) & 31, col = i & 31;
        int k   = ci * 64 + (row & 7) * 8 + (col & 7);
        int pos = (row >> 3) * 4 + (col >> 3);
        __half h0 = __float2half_rn(v);
        __half h1 = __float2half_rn(v - __half2float(h0));
        int r = pos * KE2;
        xsm[r + k]       = h0;
        xsm[r + 192 + k] = h1;
        xsm[r + 384 + k] = h0;
    }
    __syncthreads();
    uint4* dst = reinterpret_cast<uint4*>(g_X + (size_t)s * NPOS * KE2);
    const uint4* src = reinterpret_cast<const uint4*>(xsm);
    for (int g = t; g < NPOS * KE2 / 8; g += 128) dst[g] = src[g];
}

// ---------------------------------------------------------------------------
// Fused GEMM + norms: F[640, 64] per block via mma.sync m16n8k16 f16->f32,
// then per-position L2-norm + avg-pool + final L2-norm -> g_u (4 images/block).
// smem: B tile [64][584h] (73 KB) + A double-buffer [2][640][40h] (100 KB)
//       + ssq/ss2/vsm epilogue scratch.
// ---------------------------------------------------------------------------
#define OFF_B   0
#define OFF_A   74752
#define ABUF_SZ 51200
#define OFF_SSQ 177152
#define OFF_SS2 177408
#define OFF_VSM 177424
#define SMT     187664
#define BST     584            // B smem row stride (halves)
#define AST     40             // A smem row stride (halves)

__global__ void __launch_bounds__(640, 1) k_gemm() {
    extern __shared__ char sm[];
    const int t = threadIdx.x, w = t >> 5, lane = t & 31;
    const int bid = blockIdx.x;
    const uint32_t sb = smem_u32(sm);
    float* ssq = reinterpret_cast<float*>(sm + OFF_SSQ);
    float* ss2 = reinterpret_cast<float*>(sm + OFF_SS2);
    float* vsm = reinterpret_cast<float*>(sm + OFF_VSM);

    if (t < 64) ssq[t] = 0.f;
    if (t < 4)  ss2[t] = 0.f;

    // --- issue A chunk via cp.async (4 x 16B per thread) ---
    auto issueA = [&](int c, int buf) {
        const size_t kc = (size_t)32 * c;
#pragma unroll
        for (int i = 0; i < 4; i++) {
            int g = t + 640 * i;
            int row = g >> 2, part = g & 3;
            const __half* src = g_W + (size_t)row * KE2 + kc + part * 8;
            uint32_t dst = sb + OFF_A + buf * ABUF_SZ + (row * AST + part * 8) * 2;
            asm volatile("cp.async.cg.shared.global [%0], [%1], 16;"
                         :: "r"(dst), "l"(src));
        }
    };
    issueA(0, 0);
    asm volatile("cp.async.commit_group;");

    // --- stage B (X tile, 64 rows) into smem with padded stride ---
    const __half* Xb = g_X + (size_t)bid * TNB * KE2;
    for (int g = t; g < 64 * 72; g += 640) {
        int row = g / 72, part = g % 72;
        uint4 v = *reinterpret_cast<const uint4*>(Xb + (size_t)row * KE2 + part * 8);
        *reinterpret_cast<uint4*>(sm + OFF_B + row * (BST * 2) + part * 16) = v;
    }

    float acc[2][8][4];
#pragma unroll
    for (int mt = 0; mt < 2; mt++)
#pragma unroll
        for (int nt = 0; nt < 8; nt++)
#pragma unroll
            for (int c = 0; c < 4; c++) acc[mt][nt][c] = 0.f;

    // per-thread fragment base addresses (bytes)
    const uint32_t aBase = sb + OFF_A +
        ((w * 32 + (lane >> 2)) * AST + (lane & 3) * 2) * 2;
    const uint32_t bBase = sb + OFF_B +
        ((lane >> 2) * BST + (lane & 3) * 2) * 2;

    for (int c = 0; c < NCH; c++) {
        const int buf = c & 1;
        if (c + 1 < NCH) {
            issueA(c + 1, buf ^ 1);
            asm volatile("cp.async.commit_group;");
            asm volatile("cp.async.wait_group 1;");
        } else {
            asm volatile("cp.async.wait_group 0;");
        }
        __syncthreads();

#pragma unroll
        for (int ks = 0; ks < 2; ks++) {
            uint32_t a[2][4];
#pragma unroll
            for (int mt = 0; mt < 2; mt++) {
                uint32_t ad = aBase + buf * ABUF_SZ + mt * (16 * AST * 2) + ks * 32;
                asm volatile("ld.shared.b32 %0,[%1];" : "=r"(a[mt][0]) : "r"(ad));
                asm volatile("ld.shared.b32 %0,[%1];" : "=r"(a[mt][1]) : "r"(ad + 8 * AST * 2));
                asm volatile("ld.shared.b32 %0,[%1];" : "=r"(a[mt][2]) : "r"(ad + 16));
                asm volatile("ld.shared.b32 %0,[%1];" : "=r"(a[mt][3]) : "r"(ad + 8 * AST * 2 + 16));
            }
#pragma unroll
            for (int nt = 0; nt < 8; nt++) {
                uint32_t bd = bBase + nt * (8 * BST * 2) + c * 64 + ks * 32;
                uint32_t b0, b1;
                asm volatile("ld.shared.b32 %0,[%1];" : "=r"(b0) : "r"(bd));
                asm volatile("ld.shared.b32 %0,[%1];" : "=r"(b1) : "r"(bd + 16));
#pragma unroll
                for (int mt = 0; mt < 2; mt++) {
                    asm volatile(
                        "mma.sync.aligned.m16n8k16.row.col.f32.f16.f16.f32 "
                        "{%0,%1,%2,%3},{%4,%5,%6,%7},{%8,%9},{%0,%1,%2,%3};"
                        : "+f"(acc[mt][nt][0]), "+f"(acc[mt][nt][1]),
                          "+f"(acc[mt][nt][2]), "+f"(acc[mt][nt][3])
                        : "r"(a[mt][0]), "r"(a[mt][1]), "r"(a[mt][2]), "r"(a[mt][3]),
                          "r"(b0), "r"(b1));
                }
            }
        }
        __syncthreads();
    }

    // ---- epilogue: per-position channel L2-norm ----
    {
        float cs[16];
#pragma unroll
        for (int nt = 0; nt < 8; nt++)
#pragma unroll
            for (int par = 0; par < 2; par++) {
                float s = 0.f;
#pragma unroll
                for (int mt = 0; mt < 2; mt++) {
                    float x0 = acc[mt][nt][par], x1 = acc[mt][nt][2 + par];
                    s = fmaf(x0, x0, s);
                    s = fmaf(x1, x1, s);
                }
                cs[nt * 2 + par] = s;
            }
#pragma unroll
        for (int i = 0; i < 16; i++) {
            cs[i] += __shfl_xor_sync(0xffffffffu, cs[i], 4);
            cs[i] += __shfl_xor_sync(0xffffffffu, cs[i], 8);
            cs[i] += __shfl_xor_sync(0xffffffffu, cs[i], 16);
        }
        if (lane < 4) {
#pragma unroll
            for (int nt = 0; nt < 8; nt++)
#pragma unroll
                for (int par = 0; par < 2; par++)
                    atomicAdd(&ssq[nt * 8 + lane * 2 + par], cs[nt * 2 + par]);
        }
    }
    __syncthreads();
    if (t < 64) ssq[t] = 1.f / fmaxf(sqrtf(ssq[t]), 1e-12f);
    __syncthreads();

    // ---- pool over positions + final channel L2-norm ----
    float sq[4] = {0.f, 0.f, 0.f, 0.f};
#pragma unroll
    for (int mt = 0; mt < 2; mt++)
#pragma unroll
        for (int h = 0; h < 2; h++)
#pragma unroll
            for (int j = 0; j < 4; j++) {
                float s = 0.f;
#pragma unroll
                for (int ntl = 0; ntl < 2; ntl++) {
                    int nt = 2 * j + ntl;
#pragma unroll
                    for (int par = 0; par < 2; par++) {
                        int col = nt * 8 + (lane & 3) * 2 + par;
                        s = fmaf(acc[mt][nt][h * 2 + par], ssq[col], s);
                    }
                }
                s += __shfl_xor_sync(0xffffffffu, s, 1);
                s += __shfl_xor_sync(0xffffffffu, s, 2);
                if ((lane & 3) == 0) {
                    int row = w * 32 + mt * 16 + h * 8 + (lane >> 2);
                    float v = s * 0.0625f;
                    vsm[row * 4 + j] = v;
                    sq[j] = fmaf(v, v, sq[j]);
                }
            }
#pragma unroll
    for (int j = 0; j < 4; j++) {
        sq[j] += __shfl_xor_sync(0xffffffffu, sq[j], 4);
        sq[j] += __shfl_xor_sync(0xffffffffu, sq[j], 8);
        sq[j] += __shfl_xor_sync(0xffffffffu, sq[j], 16);
    }
    if (lane == 0)
#pragma unroll
        for (int j = 0; j < 4; j++) atomicAdd(&ss2[j], sq[j]);
    __syncthreads();
    if (t < 4) ss2[t] = 1.f / fmaxf(sqrtf(ss2[t]), 1e-12f);
    __syncthreads();

    for (int g = t; g < 2560; g += 640) {
        int ch = g >> 2, j = g & 3;
        g_u[(size_t)(4 * bid + j) * CO + ch] = vsm[ch * 4 + j] * ss2[j];
    }
}

// ---------------------------------------------------------------------------
// Sim + greedy pruning (round-1 version: 600 blocks, 128 threads).
// ---------------------------------------------------------------------------
#define QSTRIDE 644

__global__ void __launch_bounds__(128) k_sim(float* __restrict__ out) {
    __shared__ float qsm[9 * QSTRIDE];
    __shared__ float ssm[9 * QSTRIDE];
    __shared__ float simm[81];

    const int b = blockIdx.x / NQ_;
    const int n = blockIdx.x % NQ_;
    const int t = threadIdx.x;

    const float* qb = g_u + ((size_t)(b * 80 + WAY_ + n) * P_) * CO;
    for (int i = t; i < 9 * 160; i += 128) {
        int r = i / 160, c4 = (i % 160) * 4;
        *reinterpret_cast<float4*>(&qsm[r * QSTRIDE + c4]) =
            *reinterpret_cast<const float4*>(qb + (size_t)r * CO + c4);
    }

    for (int m = 0; m < WAY_; m++) {
        const float* sb2 = g_u + ((size_t)(b * 80 + m) * P_) * CO;
        __syncthreads();
        for (int i = t; i < 9 * 160; i += 128) {
            int r = i / 160, c4 = (i % 160) * 4;
            *reinterpret_cast<float4*>(&ssm[r * QSTRIDE + c4]) =
                *reinterpret_cast<const float4*>(sb2 + (size_t)r * CO + c4);
        }
        __syncthreads();

        if (t < 81) {
            const int h = t / 9, wq = t % 9;
            const float* sr = &ssm[h * QSTRIDE];
            const float* qr = &qsm[wq * QSTRIDE];
            float d = 0.f;
            for (int c = 0; c < CO; c += 4) {
                float4 a = *reinterpret_cast<const float4*>(sr + c);
                float4 q = *reinterpret_cast<const float4*>(qr + c);
                d = fmaf(a.x, q.x, d);
                d = fmaf(a.y, q.y, d);
                d = fmaf(a.z, q.z, d);
                d = fmaf(a.w, q.w, d);
            }
            simm[t] = d;
        }
        __syncthreads();

        if (t < 32) {
            float v0 = simm[t];
            float v1 = simm[t + 32];
            float v2 = (t + 64 < 81) ? simm[t + 64] : -1e30f;
            unsigned rmask = 0x1FFu, cmask = 0x1FFu;
            float totalv = 0.f, beta = 1.f;
            for (int it = 0; it < 9; it++) {
                float bv = -1e30f;
                int bidx = 999;
                int j = t;
                if (((rmask >> (j / 9)) & 1) && ((cmask >> (j % 9)) & 1)) {
                    bv = v0; bidx = j;
                }
                j = t + 32;
                if (((rmask >> (j / 9)) & 1) && ((cmask >> (j % 9)) & 1)) {
                    if (v1 > bv || (v1 == bv && j < bidx)) { bv = v1; bidx = j; }
                }
                j = t + 64;
                if (j < 81 && ((rmask >> (j / 9)) & 1) && ((cmask >> (j % 9)) & 1)) {
                    if (v2 > bv || (v2 == bv && j < bidx)) { bv = v2; bidx = j; }
                }
#pragma unroll
                for (int off = 16; off; off >>= 1) {
                    float ov = __shfl_xor_sync(0xffffffffu, bv, off);
                    int   oi = __shfl_xor_sync(0xffffffffu, bidx, off);
                    if (ov > bv || (ov == bv && oi < bidx)) { bv = ov; bidx = oi; }
                }
                totalv = fmaf(fmaxf(bv, 0.f), beta, totalv);
                beta *= 0.5f;
                rmask &= ~(1u << (bidx / 9));
                cmask &= ~(1u << (bidx % 9));
            }
            if (t == 0) out[((size_t)b * NQ_ + n) * WAY_ + m] = totalv;
        }
    }
}

// ---------------------------------------------------------------------------
extern "C" void kernel_launch(void* const* d_in, const int* in_sizes, int n_in,
                              void* d_out, int out_size) {
    const float* data   = (const float*)d_in[0];
    const float* conv_w = (const float*)d_in[1];
    (void)in_sizes; (void)n_in; (void)out_size;

    static bool attr_set = false;
    if (!attr_set) {
        cudaFuncSetAttribute(k_gemm, cudaFuncAttributeMaxDynamicSharedMemorySize, SMT);
        attr_set = true;
    }

    k_prepw<<<(CO * KD + 255) / 256, 256>>>(conv_w);
    k_prepx<<<NS, 128>>>(data);
    k_gemm<<<NTOT / TNB, 640, SMT>>>();
    k_sim<<<B_ * NQ_, 128>>>((float*)d_out);
}